// round 9
// baseline (speedup 1.0000x reference)
#include <cuda_runtime.h>
#include <cuda_bf16.h>
#include <math.h>

#define NG    1024
#define IMG   256
#define TILE  16
#define NTIL  (IMG / TILE)      // 16 -> 256 render blocks
#define HW    (IMG * IMG)
#define NT    256
#define MAXP  516               // pair slots: 1024/2 + pad
#define NWORD 32                // 1024 bits per tile

typedef unsigned long long u64;

// Global scratch (no allocations; zero-initialized at module load).
// Mask is filled by idempotent atomicOr with identical bits every call ->
// deterministic and replay-safe without clearing.
__device__ float4       g_P0[NG];              // {-cx, -cy, ka, kb}
__device__ float4       g_P1[NG];              // { kc,  fr, fg, fb}
__device__ unsigned int g_mask[NTIL * NTIL * NWORD];

// ---- hardware MUFU ----
__device__ __forceinline__ float ex2a(float x) {
    float y; asm("ex2.approx.f32 %0, %1;" : "=f"(y) : "f"(x)); return y;
}
__device__ __forceinline__ float rcpa(float x) {
    float y; asm("rcp.approx.f32 %0, %1;" : "=f"(y) : "f"(x)); return y;
}

// ---- packed f32x2 ----
__device__ __forceinline__ u64 fma2(u64 a, u64 b, u64 c) {
    u64 d; asm("fma.rn.f32x2 %0, %1, %2, %3;" : "=l"(d) : "l"(a), "l"(b), "l"(c)); return d;
}
__device__ __forceinline__ u64 mul2(u64 a, u64 b) {
    u64 d; asm("mul.rn.f32x2 %0, %1, %2;" : "=l"(d) : "l"(a), "l"(b)); return d;
}
__device__ __forceinline__ u64 add2(u64 a, u64 b) {
    u64 d; asm("add.rn.f32x2 %0, %1, %2;" : "=l"(d) : "l"(a), "l"(b)); return d;
}
__device__ __forceinline__ u64 pack2(float lo, float hi) {
    u64 d; asm("mov.b64 %0, {%1, %2};" : "=l"(d) : "f"(lo), "f"(hi)); return d;
}
__device__ __forceinline__ void unpack2(u64 v, float& lo, float& hi) {
    asm("mov.b64 {%0, %1}, %2;" : "=f"(lo), "=f"(hi) : "l"(v));
}

// ======================= prep: params + tile binning =======================
__global__ void prep_kernel(const float* __restrict__ xyz,
                            const float* __restrict__ chol,
                            const float* __restrict__ opac,
                            const float* __restrict__ feat)
{
    int i = blockIdx.x * blockDim.x + threadIdx.x;
    if (i >= NG) return;

    const float K2L2E = 2.8853900817779268f;   // 2*log2(e)
    const float L2E   = 1.4426950408889634f;
    const float T2    = 28.0f;                 // 2*T, T = 14 nats

    float2 xy = ((const float2*)xyz)[i];
    float ux = ex2a(xy.x * K2L2E);
    float uy = ex2a(xy.y * K2L2E);
    float cx = fmaf(rcpa(ux + 1.0f), -256.0f, 256.0f);   // 128*(tanh+1)
    float cy = fmaf(rcpa(uy + 1.0f), -256.0f, 256.0f);

    float l1 = chol[3 * i + 0] + 0.5f;
    float l2 = chol[3 * i + 1];
    float l3 = chol[3 * i + 2] + 0.5f;
    float a  = l1 * l1;
    float b  = l1 * l2;
    float cc = fmaf(l2, l2, l3 * l3);
    float inv = rcpa(fmaf(a, cc, -(b * b)));

    float o = opac[i];
    g_P0[i] = make_float4(-cx, -cy, -0.5f * L2E * cc * inv, L2E * b * inv);
    g_P1[i] = make_float4(-0.5f * L2E * a * inv,
                          feat[3 * i + 0] * o,
                          feat[3 * i + 1] * o,
                          feat[3 * i + 2] * o);

    // tile AABB: |dx| <= sqrt(2T*Sxx), |dy| <= sqrt(2T*Syy)
    float wx = sqrtf(T2 * a);
    float wy = sqrtf(T2 * cc);
    int tx0 = max(0,        (int)ceilf ((cx - wx - 15.5f) * 0.0625f));
    int tx1 = min(NTIL - 1, (int)floorf((cx + wx -  0.5f) * 0.0625f));
    int ty0 = max(0,        (int)ceilf ((cy - wy - 15.5f) * 0.0625f));
    int ty1 = min(NTIL - 1, (int)floorf((cy + wy -  0.5f) * 0.0625f));

    unsigned bit  = 1u << (i & 31);
    int      word = i >> 5;
    for (int ty = ty0; ty <= ty1; ty++)
        for (int tx = tx0; tx <= tx1; tx++)
            atomicOr(&g_mask[(ty * NTIL + tx) * NWORD + word], bit);
}

// ======================= render: O(count) per tile =======================
__global__ __launch_bounds__(NT, 2)
void render_kernel(float* __restrict__ out)
{
    __shared__ __align__(16) float4 s_A[MAXP];   // {ncx2, ncy2}
    __shared__ __align__(16) float4 s_B[MAXP];   // {ka2,  kb2}
    __shared__ __align__(16) float4 s_C[MAXP];   // {kc2,  fr2}
    __shared__ __align__(16) float4 s_D[MAXP];   // {fg2,  fb2}
    __shared__ short s_idx[NG];
    __shared__ int   s_count;

    const int tid  = threadIdx.x;
    const int warp = tid >> 5;
    const int lane = tid & 31;
    const int tile = blockIdx.y * NTIL + blockIdx.x;

    // warp 0: expand mask -> ascending-index list (deterministic)
    if (warp == 0) {
        unsigned w = g_mask[tile * NWORD + lane];
        int cnt = __popc(w);
        int incl = cnt;
        #pragma unroll
        for (int d = 1; d < 32; d <<= 1) {
            int v = __shfl_up_sync(0xffffffffu, incl, d);
            if (lane >= d) incl += v;
        }
        int base = incl - cnt;
        while (w) {
            int b = __ffs(w) - 1;
            w &= w - 1;
            s_idx[base++] = (short)(lane * 32 + b);
        }
        if (lane == 31) s_count = incl;
    }
    __syncthreads();

    const int count = s_count;
    float* sAf = (float*)s_A;
    float* sBf = (float*)s_B;
    float* sCf = (float*)s_C;
    float* sDf = (float*)s_D;

    // copy hit params L2 -> smem (pair-interleaved for LDS.128 splat)
    for (int i = tid; i < count; i += NT) {
        int g = s_idx[i];
        float4 P0 = g_P0[g];
        float4 P1 = g_P1[g];
        int p = i >> 1, h = i & 1, base = 4 * p + h;
        sAf[base] = P0.x;  sAf[base + 2] = P0.y;
        sBf[base] = P0.z;  sBf[base + 2] = P0.w;
        sCf[base] = P1.x;  sCf[base + 2] = P1.y;
        sDf[base] = P1.z;  sDf[base + 2] = P1.w;
    }
    if (tid == 0) {   // NaN-safe pad for odd tail
        #pragma unroll
        for (int s = 0; s < 2; s++) {
            int k = count + s;
            int p = k >> 1, h = k & 1, base = 4 * p + h;
            sAf[base] = 0.0f; sAf[base + 2] = 0.0f;
            sBf[base] = 0.0f; sBf[base + 2] = 0.0f;
            sCf[base] = 0.0f; sCf[base + 2] = 0.0f;
            sDf[base] = 0.0f; sDf[base + 2] = 0.0f;
        }
    }
    __syncthreads();

    // splat: one pixel per thread, 2 gaussians per iter
    const int   pxi = blockIdx.x * TILE + (tid & (TILE - 1));
    const int   pyi = blockIdx.y * TILE + (tid >> 4);
    const float px  = (float)pxi + 0.5f;
    const float py  = (float)pyi + 0.5f;

    const u64 px2 = pack2(px, px);
    const u64 py2 = pack2(py, py);
    u64 accr2 = 0ull, accg2 = 0ull, accb2 = 0ull;

    const ulonglong2* pA = (const ulonglong2*)s_A;
    const ulonglong2* pB = (const ulonglong2*)s_B;
    const ulonglong2* pC = (const ulonglong2*)s_C;
    const ulonglong2* pD = (const ulonglong2*)s_D;

    const int pairs = (count + 1) >> 1;
    #pragma unroll 2
    for (int i = 0; i < pairs; i++) {
        ulonglong2 A = pA[i];                  // LDS.128 broadcast
        ulonglong2 B = pB[i];
        ulonglong2 C = pC[i];
        ulonglong2 D = pD[i];
        u64 dx2 = add2(px2, A.x);
        u64 dy2 = add2(py2, A.y);
        u64 u   = fma2(B.y, dy2, mul2(B.x, dx2));          // ka*dx + kb*dy
        u64 t2  = fma2(dx2, u, mul2(mul2(C.x, dy2), dy2)); // + kc*dy^2
        float tl, th; unpack2(t2, tl, th);
        u64 w2  = pack2(ex2a(tl), ex2a(th));               // MUFU.EX2
        accr2 = fma2(w2, C.y, accr2);
        accg2 = fma2(w2, D.x, accg2);
        accb2 = fma2(w2, D.y, accb2);
    }

    float rl, rh, gl, gh, bl, bh;
    unpack2(accr2, rl, rh); unpack2(accg2, gl, gh); unpack2(accb2, bl, bh);
    float accr = fminf(fmaxf(rl + rh, 0.0f), 1.0f);
    float accg = fminf(fmaxf(gl + gh, 0.0f), 1.0f);
    float accb = fminf(fmaxf(bl + bh, 0.0f), 1.0f);

    const int p = pyi * IMG + pxi;
    out[0 * HW + p] = accr;
    out[1 * HW + p] = accg;
    out[2 * HW + p] = accb;
}

extern "C" void kernel_launch(void* const* d_in, const int* in_sizes, int n_in,
                              void* d_out, int out_size)
{
    const float* xyz  = (const float*)d_in[0];   // (N,2)
    const float* chol = (const float*)d_in[1];   // (N,3)
    const float* opac = (const float*)d_in[2];   // (N,1)
    const float* feat = (const float*)d_in[3];   // (N,3)
    float* out = (float*)d_out;                  // (1,3,256,256)

    prep_kernel<<<NG / NT, NT>>>(xyz, chol, opac, feat);
    dim3 grid(NTIL, NTIL);                       // 16x16 = 256 blocks
    render_kernel<<<grid, NT>>>(out);
}

// round 10
// speedup vs baseline: 1.3092x; 1.3092x over previous
#include <cuda_runtime.h>
#include <cuda_bf16.h>
#include <math.h>

#define NG    1024
#define IMG   256
#define TILE  16
#define NTIL  (IMG / TILE)      // 16 -> 256 blocks, 1 kernel, 1 T_ovh
#define HW    (IMG * IMG)
#define NT    256
#define GPT   4
#define MAXP  516               // pair slots: 1024/2 + pad

typedef unsigned long long u64;

// ---- hardware MUFU ----
__device__ __forceinline__ float ex2a(float x) {
    float y; asm("ex2.approx.f32 %0, %1;" : "=f"(y) : "f"(x)); return y;
}
__device__ __forceinline__ float rcpa(float x) {
    float y; asm("rcp.approx.f32 %0, %1;" : "=f"(y) : "f"(x)); return y;
}

// ---- packed f32x2 ----
__device__ __forceinline__ u64 fma2(u64 a, u64 b, u64 c) {
    u64 d; asm("fma.rn.f32x2 %0, %1, %2, %3;" : "=l"(d) : "l"(a), "l"(b), "l"(c)); return d;
}
__device__ __forceinline__ u64 mul2(u64 a, u64 b) {
    u64 d; asm("mul.rn.f32x2 %0, %1, %2;" : "=l"(d) : "l"(a), "l"(b)); return d;
}
__device__ __forceinline__ u64 add2(u64 a, u64 b) {
    u64 d; asm("add.rn.f32x2 %0, %1, %2;" : "=l"(d) : "l"(a), "l"(b)); return d;
}
__device__ __forceinline__ u64 pack2(float lo, float hi) {
    u64 d; asm("mov.b64 %0, {%1, %2};" : "=l"(d) : "f"(lo), "f"(hi)); return d;
}
__device__ __forceinline__ void unpack2(u64 v, float& lo, float& hi) {
    asm("mov.b64 {%0, %1}, %2;" : "=f"(lo), "=f"(hi) : "l"(v));
}

// Pair-interleaved SoA smem: s_A {ncx2,ncy2}, s_B {ka2,kb2}, s_C {kc2,fr2}, s_D {fg2,fb2}
__global__ __launch_bounds__(NT, 2)
void fused_render_kernel(const float* __restrict__ xyz,
                         const float* __restrict__ chol,
                         const float* __restrict__ opac,
                         const float* __restrict__ feat,
                         float* __restrict__ out)
{
    __shared__ __align__(16) float4 s_A[MAXP];
    __shared__ __align__(16) float4 s_B[MAXP];
    __shared__ __align__(16) float4 s_C[MAXP];
    __shared__ __align__(16) float4 s_D[MAXP];
    __shared__ int s_warpcnt[NT / 32];

    const int tid  = threadIdx.x;
    const int warp = tid >> 5;
    const int lane = tid & 31;

    const float x0  = (float)(blockIdx.x * TILE);
    const float y0  = (float)(blockIdx.y * TILE);
    const float xlo = x0 + 0.5f, xhi = x0 + (float)TILE - 0.5f;
    const float ylo = y0 + 0.5f, yhi = y0 + (float)TILE - 0.5f;

    // ---- batched contiguous raw loads: thread t owns gaussians 4t..4t+3 ----
    const float4* xyz4 = (const float4*)xyz;
    const float4* ch4  = (const float4*)chol;
    const float4* op4  = (const float4*)opac;
    const float4* ft4  = (const float4*)feat;

    float4 xyA = xyz4[tid * 2 + 0];
    float4 xyB = xyz4[tid * 2 + 1];
    float4 chA = ch4[tid * 3 + 0];
    float4 chB = ch4[tid * 3 + 1];
    float4 chC = ch4[tid * 3 + 2];
    float4 opV = op4[tid];
    float4 ftA = ft4[tid * 3 + 0];
    float4 ftB = ft4[tid * 3 + 1];
    float4 ftC = ft4[tid * 3 + 2];

    float xyv[8]  = {xyA.x, xyA.y, xyA.z, xyA.w, xyB.x, xyB.y, xyB.z, xyB.w};
    float chv[12] = {chA.x, chA.y, chA.z, chA.w, chB.x, chB.y, chB.z, chB.w,
                     chC.x, chC.y, chC.z, chC.w};
    float ftv[12] = {ftA.x, ftA.y, ftA.z, ftA.w, ftB.x, ftB.y, ftB.z, ftB.w,
                     ftC.x, ftC.y, ftC.z, ftC.w};
    float opv[4]  = {opV.x, opV.y, opV.z, opV.w};

    // ---- prep + AABB cull (HW MUFU only) ----
    const float K2L2E = 2.8853900817779268f;   // 2*log2(e)
    const float T2    = 25.0f;                 // 2*T, T = 12.5 nats
    float cxv[GPT], cyv[GPT], av[GPT], bv[GPT], cv[GPT];
    bool  hitv[GPT];

    #pragma unroll
    for (int j = 0; j < GPT; j++) {
        float ux = ex2a(xyv[2 * j + 0] * K2L2E);
        float uy = ex2a(xyv[2 * j + 1] * K2L2E);
        float cx = fmaf(rcpa(ux + 1.0f), -256.0f, 256.0f);   // 128*(tanh+1)
        float cy = fmaf(rcpa(uy + 1.0f), -256.0f, 256.0f);

        float l1 = chv[3 * j + 0] + 0.5f;
        float l2 = chv[3 * j + 1];
        float l3 = chv[3 * j + 2] + 0.5f;

        float a  = l1 * l1;                 // Sigma_xx
        float b  = l1 * l2;                 // Sigma_xy
        float cc = fmaf(l2, l2, l3 * l3);   // Sigma_yy

        float dxc = fminf(fmaxf(cx, xlo), xhi) - cx;
        float dyc = fminf(fmaxf(cy, ylo), yhi) - cy;
        bool hit = (dxc * dxc <= T2 * a) && (dyc * dyc <= T2 * cc);

        cxv[j] = cx; cyv[j] = cy; av[j] = a; bv[j] = b; cv[j] = cc;
        hitv[j] = hit;
    }

    // ---- ballot compaction (no serial shuffle scan; deterministic order) ----
    unsigned mj[GPT];
    int wc = 0;
    #pragma unroll
    for (int j = 0; j < GPT; j++) {
        mj[j] = __ballot_sync(0xffffffffu, hitv[j]);
        wc += __popc(mj[j]);
    }
    if (lane == 0) s_warpcnt[warp] = wc;
    __syncthreads();

    int wbase = 0, count = 0;
    #pragma unroll
    for (int w = 0; w < NT / 32; w++) {
        int v = s_warpcnt[w];
        if (w < warp) wbase += v;
        count += v;
    }

    float* sAf = (float*)s_A;
    float* sBf = (float*)s_B;
    float* sCf = (float*)s_C;
    float* sDf = (float*)s_D;

    const float L2E = 1.4426950408889634f;
    const unsigned lt = (1u << lane) - 1u;
    {
        int jbase = wbase;
        #pragma unroll
        for (int j = 0; j < GPT; j++) {
            if (hitv[j]) {
                int off = jbase + __popc(mj[j] & lt);
                float inv = rcpa(fmaf(av[j], cv[j], -(bv[j] * bv[j])));
                float o = opv[j];
                int p = off >> 1, h = off & 1, base = 4 * p + h;
                sAf[base]     = -cxv[j];
                sAf[base + 2] = -cyv[j];
                sBf[base]     = -0.5f * L2E * cv[j] * inv;
                sBf[base + 2] =  L2E * bv[j] * inv;
                sCf[base]     = -0.5f * L2E * av[j] * inv;
                sCf[base + 2] = ftv[3 * j + 0] * o;
                sDf[base]     = ftv[3 * j + 1] * o;
                sDf[base + 2] = ftv[3 * j + 2] * o;
            }
            jbase += __popc(mj[j]);
        }
    }
    if (tid == 0) {   // NaN-safe pad for odd pair tail
        #pragma unroll
        for (int s = 0; s < 2; s++) {
            int k = count + s;
            int p = k >> 1, h = k & 1, base = 4 * p + h;
            sAf[base] = 0.0f; sAf[base + 2] = 0.0f;
            sBf[base] = 0.0f; sBf[base + 2] = 0.0f;
            sCf[base] = 0.0f; sCf[base + 2] = 0.0f;
            sDf[base] = 0.0f; sDf[base + 2] = 0.0f;
        }
    }
    __syncthreads();

    // ---- packed f32x2 splat: one pixel per thread, 2 gaussians/iter ----
    const int   pxi = blockIdx.x * TILE + (tid & (TILE - 1));
    const int   pyi = blockIdx.y * TILE + (tid >> 4);
    const float px  = (float)pxi + 0.5f;
    const float py  = (float)pyi + 0.5f;

    const u64 px2 = pack2(px, px);
    const u64 py2 = pack2(py, py);
    u64 accr2 = 0ull, accg2 = 0ull, accb2 = 0ull;

    const ulonglong2* pA = (const ulonglong2*)s_A;
    const ulonglong2* pB = (const ulonglong2*)s_B;
    const ulonglong2* pC = (const ulonglong2*)s_C;
    const ulonglong2* pD = (const ulonglong2*)s_D;

    const int pairs = (count + 1) >> 1;
    #pragma unroll 2
    for (int i = 0; i < pairs; i++) {
        ulonglong2 A = pA[i];                  // LDS.128 broadcast
        ulonglong2 B = pB[i];
        ulonglong2 C = pC[i];
        ulonglong2 D = pD[i];
        u64 dx2 = add2(px2, A.x);
        u64 dy2 = add2(py2, A.y);
        u64 u   = fma2(B.y, dy2, mul2(B.x, dx2));          // ka*dx + kb*dy
        u64 t2  = fma2(dx2, u, mul2(mul2(C.x, dy2), dy2)); // + kc*dy^2
        float tl, th; unpack2(t2, tl, th);
        u64 w2  = pack2(ex2a(tl), ex2a(th));               // MUFU.EX2
        accr2 = fma2(w2, C.y, accr2);
        accg2 = fma2(w2, D.x, accg2);
        accb2 = fma2(w2, D.y, accb2);
    }

    float rl, rh, gl, gh, bl, bh;
    unpack2(accr2, rl, rh); unpack2(accg2, gl, gh); unpack2(accb2, bl, bh);
    float accr = fminf(fmaxf(rl + rh, 0.0f), 1.0f);
    float accg = fminf(fmaxf(gl + gh, 0.0f), 1.0f);
    float accb = fminf(fmaxf(bl + bh, 0.0f), 1.0f);

    const int p = pyi * IMG + pxi;
    out[0 * HW + p] = accr;
    out[1 * HW + p] = accg;
    out[2 * HW + p] = accb;
}

extern "C" void kernel_launch(void* const* d_in, const int* in_sizes, int n_in,
                              void* d_out, int out_size)
{
    const float* xyz  = (const float*)d_in[0];   // (N,2)
    const float* chol = (const float*)d_in[1];   // (N,3)
    const float* opac = (const float*)d_in[2];   // (N,1)
    const float* feat = (const float*)d_in[3];   // (N,3)
    float* out = (float*)d_out;                  // (1,3,256,256)

    dim3 grid(NTIL, NTIL);                       // 16x16 = 256 blocks, ONE kernel
    fused_render_kernel<<<grid, NT>>>(xyz, chol, opac, feat, out);
}